// round 17
// baseline (speedup 1.0000x reference)
#include <cuda_runtime.h>

#define NBATCH 4096
#define TT     2048
#define SDIM   5
#define CHUNK  8                 // delta steps staged per smem refill
#define NCHUNK (TT / CHUNK)

typedef unsigned long long ull;

// compiler-only barrier: forbids C++/ptxas reordering of smem ops across it.
// HW ordering within a single converged warp is guaranteed by the in-order
// per-warp LSU pipeline (uniform control flow -> no divergence anywhere).
#define CBAR() asm volatile("" ::: "memory")

// ---- packed f32x2 helpers (sm_100+/sm_103a) ----
__device__ __forceinline__ ull pack2(float lo, float hi) {
    ull r; asm("mov.b64 %0, {%1, %2};" : "=l"(r) : "f"(lo), "f"(hi)); return r;
}
__device__ __forceinline__ void unpack2(ull a, float& lo, float& hi) {
    asm("mov.b64 {%0, %1}, %2;" : "=f"(lo), "=f"(hi) : "l"(a));
}
__device__ __forceinline__ float sum2(ull a) {
    float lo, hi; asm("mov.b64 {%0, %1}, %2;" : "=f"(lo), "=f"(hi) : "l"(a));
    return lo + hi;
}
__device__ __forceinline__ ull dup2(float v) {          // (v, v)
    ull r; asm("mov.b64 %0, {%1, %1};" : "=l"(r) : "f"(v)); return r;
}
__device__ __forceinline__ ull mul2(ull a, ull b) {
    ull d; asm("mul.rn.f32x2 %0, %1, %2;" : "=l"(d) : "l"(a), "l"(b)); return d;
}
__device__ __forceinline__ ull add2(ull a, ull b) {
    ull d; asm("add.rn.f32x2 %0, %1, %2;" : "=l"(d) : "l"(a), "l"(b)); return d;
}
__device__ __forceinline__ void fma2(ull& d, ull a, ull b) {
    asm("fma.rn.f32x2 %0, %1, %2, %0;" : "+l"(d) : "l"(a), "l"(b));
}

#define SC 2.885390081777926815f   // 2*log2(e): folded into W2/b2 only

__device__ __forceinline__ float tanh_hw(float x) {       // stage-1 (MUFU.TANH)
    float y; asm("tanh.approx.f32 %0, %1;" : "=f"(y) : "f"(x));
    return y;
}
__device__ __forceinline__ float tanh_pre(float y) {      // stage-2 (precise, prescaled)
    float e, r;
    asm("ex2.approx.f32 %0, %1;" : "=f"(e) : "f"(y));
    asm("rcp.approx.f32 %0, %1;" : "=f"(r) : "f"(e + 1.0f));
    return fmaf(-2.0f, r, 1.0f);
}

#define SHF8(v, src) __shfl_sync(0xffffffffu, (v), (src), 8)

__global__ __launch_bounds__(32)   // 1 warp per block; regs effectively uncapped
void msc_seq_kernel(const float* __restrict__ delta,
                    const float* __restrict__ state0,
                    const float* __restrict__ W1, const float* __restrict__ b1,
                    const float* __restrict__ W2, const float* __restrict__ b2,
                    const float* __restrict__ W3, const float* __restrict__ b3,
                    float* __restrict__ out)
{
    // per-quarter lines, stride 40 floats (160B) -> quarter bases at banks 0/8/16/24
    __shared__ __align__(16) float sh1[4][40];   // h1 exchange, REUSED for h2
    __shared__ __align__(16) float shd[4][40];   // staged delta (float4 per step)

    const int lane = threadIdx.x;        // 32-thread block = one warp
    const int q    = lane >> 3;          // quarter (batch) 0..3
    const int ql   = lane & 7;           // lane within quarter
    const int b    = blockIdx.x * 4 + q; // this quarter's batch element

    const int jb = 4 * ql;               // 4 ADJACENT owned channels -> STS.128

    // ---- weights in registers ----
    ull w1p01[8], w1p23[8];              // stage-1 W1, packed by channel pair
#pragma unroll
    for (int i = 0; i < 8; i++) {
        w1p01[i] = pack2(W1[i * 32 + jb + 0], W1[i * 32 + jb + 1]);
        w1p23[i] = pack2(W1[i * 32 + jb + 2], W1[i * 32 + jb + 3]);
    }

    ull w2c[4][16];                      // W2 columns jb..jb+3, packed+prescaled
#pragma unroll
    for (int cc = 0; cc < 4; cc++)
#pragma unroll
        for (int p = 0; p < 16; p++)
            w2c[cc][p] = pack2(W2[(2 * p) * 32 + jb + cc] * SC,
                               W2[(2 * p + 1) * 32 + jb + cc] * SC);

    const ull b1p01 = pack2(b1[jb + 0], b1[jb + 1]);
    const ull b1p23 = pack2(b1[jb + 2], b1[jb + 3]);
    float b2r[4];
#pragma unroll
    for (int cc = 0; cc < 4; cc++)
        b2r[cc] = b2[jb + cc] * SC;

    // ---- slot mapping: lane's tracked channel; stage 3 = full-column dot ----
    const int t2 = (ql >> 2) & 1, t1 = (ql >> 1) & 1, t0 = ql & 1;
    const int vidx = t0 ? 4 : (t1 ? (t2 ? 3 : 2) : (t2 ? 1 : 0));
    // slot lanes per quarter: ch0<-0, ch1<-4, ch2<-2, ch3<-6, ch4<-1
    const bool wr = (ql == 0) | (ql == 1) | (ql == 2) | (ql == 4) | (ql == 6);
    const float b3v = b3[vidx];

    ull w3o[16];                         // W3 column vidx (packed over rows)
#pragma unroll
    for (int p = 0; p < 16; p++)
        w3o[p] = pack2(W3[(2 * p) * SDIM + vidx], W3[(2 * p + 1) * SDIM + vidx]);

    float stv = state0[b * SDIM + vidx]; // lane carries its slot's state channel

    const float* dptr = delta + (size_t)b * (TT * 3);
    float*       optr = out   + (size_t)b * (TT * SDIM) + vidx;

    float* line = &sh1[q][0];
    const ulonglong2* hp = (const ulonglong2*)line;

    // prefetch first delta chunk: lane (q,ql) holds step ql of batch b
    float r0 = dptr[ql * 3 + 0];
    float r1 = dptr[ql * 3 + 1];
    float r2 = dptr[ql * 3 + 2];

    for (int c = 0; c < NCHUNK; c++) {
        CBAR();                          // order: prior chunk's LDS before STS
        *(float4*)(&shd[q][ql * 4]) = make_float4(r0, r1, r2, 0.f);
        CBAR();                          // order: STS before this chunk's LDS
        if (c + 1 < NCHUNK) {
            const float* np = dptr + (size_t)(c + 1) * (CHUNK * 3);
            r0 = np[ql * 3 + 0];
            r1 = np[ql * 3 + 1];
            r2 = np[ql * 3 + 2];
        }

#pragma unroll 2
        for (int tl = 0; tl < CHUNK; tl++) {
            const float4 dv = *(const float4*)(&shd[q][tl * 4]);

            // ---- broadcast state channels within the quarter (width=8 shfl) ----
            // shfl.sync is also the warp convergence anchor each step
            const float s0 = SHF8(stv, 0);
            const float s1 = SHF8(stv, 4);
            const float s2 = SHF8(stv, 2);
            const float s3 = SHF8(stv, 6);
            const float s4 = SHF8(stv, 1);

            // ---- stage 1: packed f32x2 over channel pairs (16 fma2) ----
            const ull xd0 = dup2(dv.x);
            const ull xd1 = dup2(dv.y);
            const ull xd2 = dup2(dv.z);
            const ull xs0 = dup2(s0);
            const ull xs1 = dup2(s1);
            const ull xs2 = dup2(s2);
            const ull xs3 = dup2(s3);
            const ull xs4 = dup2(s4);

            ull acc01 = b1p01, acc23 = b1p23;
            fma2(acc01, xd0, w1p01[5]); fma2(acc23, xd0, w1p23[5]);
            fma2(acc01, xd1, w1p01[6]); fma2(acc23, xd1, w1p23[6]);
            fma2(acc01, xd2, w1p01[7]); fma2(acc23, xd2, w1p23[7]);
            fma2(acc01, xs0, w1p01[0]); fma2(acc23, xs0, w1p23[0]);
            fma2(acc01, xs1, w1p01[1]); fma2(acc23, xs1, w1p23[1]);
            fma2(acc01, xs2, w1p01[2]); fma2(acc23, xs2, w1p23[2]);
            fma2(acc01, xs3, w1p01[3]); fma2(acc23, xs3, w1p23[3]);
            fma2(acc01, xs4, w1p01[4]); fma2(acc23, xs4, w1p23[4]);

            float a0f, a1f, a2f, a3f;
            unpack2(acc01, a0f, a1f);
            unpack2(acc23, a2f, a3f);
            // 4 adjacent channels -> single STS.128 (no syncwarp: in-order LSU)
            *(float4*)(&line[jb]) = make_float4(tanh_hw(a0f), tanh_hw(a1f),
                                                tanh_hw(a2f), tanh_hw(a3f));
            CBAR();

            // ---- stage 2: 4 channels, 2 packed chains each (8 LDS.128 total) ----
            ull a0[4], a1[4];
            ulonglong2 u = hp[0];
#pragma unroll
            for (int cc = 0; cc < 4; cc++) {
                a0[cc] = mul2(u.x, w2c[cc][0]);
                a1[cc] = mul2(u.y, w2c[cc][1]);
            }
#pragma unroll
            for (int p = 1; p < 8; p++) {
                u = hp[p];
#pragma unroll
                for (int cc = 0; cc < 4; cc++) {
                    fma2(a0[cc], u.x, w2c[cc][2 * p]);
                    fma2(a1[cc], u.y, w2c[cc][2 * p + 1]);
                }
            }
            float h2v[4];
#pragma unroll
            for (int cc = 0; cc < 4; cc++)
                h2v[cc] = tanh_pre(sum2(add2(a0[cc], a1[cc])) + b2r[cc]);

            // ---- stage 3: publish h2 (reuse line), full-column dot per lane ----
            CBAR();                      // order: stage-2 LDS before h2 STS
            *(float4*)(&line[jb]) = make_float4(h2v[0], h2v[1], h2v[2], h2v[3]);
            CBAR();                      // order: h2 STS before stage-3 LDS

            ulonglong2 u2 = hp[0];
            ull o0 = mul2(u2.x, w3o[0]);
            ull o1 = mul2(u2.y, w3o[1]);
#pragma unroll
            for (int p = 1; p < 8; p++) {
                u2 = hp[p];
                fma2(o0, u2.x, w3o[2 * p]);
                fma2(o1, u2.y, w3o[2 * p + 1]);
            }
            stv += sum2(add2(o0, o1)) + b3v;   // every lane updates its channel

            if (wr) *optr = stv;         // lanes {0,4,2,6,1} -> channels {0..4}
            optr += SDIM;
        }
    }
}

extern "C" void kernel_launch(void* const* d_in, const int* in_sizes, int n_in,
                              void* d_out, int out_size)
{
    const float* delta  = (const float*)d_in[0];
    const float* state0 = (const float*)d_in[1];
    const float* W1     = (const float*)d_in[2];
    const float* b1     = (const float*)d_in[3];
    const float* W2     = (const float*)d_in[4];
    const float* b2     = (const float*)d_in[5];
    const float* W3     = (const float*)d_in[6];
    const float* b3     = (const float*)d_in[7];
    float* out = (float*)d_out;

    dim3 grid(NBATCH / 4);   // 1024 one-warp blocks, 4 batches each (8 lanes/batch)
    dim3 block(32);
    msc_seq_kernel<<<grid, block>>>(delta, state0, W1, b1, W2, b2, W3, b3, out);
}